// round 4
// baseline (speedup 1.0000x reference)
#include <cuda_runtime.h>
#include <math.h>

#define NB 4
#define HH 8
#define DD 64
#define LL 2048
#define CC 64
#define BH (NB * HH)   // 32

typedef unsigned long long ull;

// ---------------- device scratch (no allocations allowed) ----------------
__device__ float g_sim[(size_t)BH * LL * LL];   // 512 MB sim scratch
__device__ float g_p1s[BH * 512];
__device__ float g_p1q[BH * 512];
__device__ float g_p2s[BH * 32];
__device__ float g_p2q[BH * 32];
__device__ float g_escale[NB];                  // rstd1 * log2(e)
__device__ float g_mean2[NB];
__device__ float g_rstd2[NB];

// ---------------- packed f32x2 helpers (Blackwell FFMA2 path) ----------------
__device__ __forceinline__ ull pk2(float a, float b) {
    ull r; asm("mov.b64 %0,{%1,%2};" : "=l"(r) : "f"(a), "f"(b)); return r;
}
__device__ __forceinline__ float2 upk(ull p) {
    float2 r; asm("mov.b64 {%0,%1},%2;" : "=f"(r.x), "=f"(r.y) : "l"(p)); return r;
}
__device__ __forceinline__ void ffma2(ull& d, ull a, ull b) {
    asm("fma.rn.f32x2 %0,%1,%2,%0;" : "+l"(d) : "l"(a), "l"(b));
}
__device__ __forceinline__ ull ffma2r(ull a, ull b, ull c) {
    ull d; asm("fma.rn.f32x2 %0,%1,%2,%3;" : "=l"(d) : "l"(a), "l"(b), "l"(c)); return d;
}
__device__ __forceinline__ ull fmul2(ull a, ull b) {
    ull d; asm("mul.rn.f32x2 %0,%1,%2;" : "=l"(d) : "l"(a), "l"(b)); return d;
}
__device__ __forceinline__ ull fadd2(ull a, ull b) {
    ull d; asm("add.rn.f32x2 %0,%1,%2;" : "=l"(d) : "l"(a), "l"(b)); return d;
}

// packed exp(s * rstd) via exp2 polynomial, 2 elements at a time on the fma pipe
__device__ __forceinline__ ull pexp2(ull s2, ull cs2, ull MAGIC, ull NMAGIC, ull NEG1,
                                     ull C5, ull C4, ull C3, ull C2, ull C1, ull ONE2) {
    ull y = fmul2(s2, cs2);
    ull t = fadd2(y, MAGIC);           // round-to-nearest int in low mantissa
    ull u = fadd2(t, NMAGIC);          // t - magic (= round(y))
    ull f = ffma2r(u, NEG1, y);        // f = y - round(y), in [-0.5, 0.5]
    ull p = ffma2r(C5, f, C4);
    p = ffma2r(p, f, C3);
    p = ffma2r(p, f, C2);
    p = ffma2r(p, f, C1);
    p = ffma2r(p, f, ONE2);            // 2^f
    float2 tf = upk(t);
    int k0 = (__float_as_int(tf.x) << 23) + 0x3f800000;
    int k1 = (__float_as_int(tf.y) << 23) + 0x3f800000;
    ull sc = pk2(__int_as_float(k0), __int_as_float(k1));
    return fmul2(p, sc);               // 2^f * 2^k
}

// ---------------- K1: sim = Q^T K per (b,h), + per-block sum/sumsq ----------------
// block tile 64(l) x 128(m), per-thread 4x8 via packed FFMA2
__global__ void __launch_bounds__(256) k1_sim(const float* __restrict__ Q,
                                              const float* __restrict__ K) {
    __shared__ __align__(16) float Qs[64][64];
    __shared__ __align__(16) float Ks[64][128];
    const int bh = blockIdx.z;
    const int l0 = blockIdx.y * 64;
    const int m0 = blockIdx.x * 128;
    const int t  = threadIdx.x;
    const int tm = t & 15;     // 0..15 (cols tm*4 and 64+tm*4)
    const int tr = t >> 4;     // 0..15 (rows tr*4..tr*4+3)

    const float* qb = Q + (size_t)bh * DD * LL + l0;
    const float* kb = K + (size_t)bh * DD * LL + m0;

    #pragma unroll
    for (int p = 0; p < 4; p++) {
        int idx = p * 256 + t;
        int d = idx >> 4, c = idx & 15;
        *(float4*)&Qs[d][c * 4] = *(const float4*)(qb + (size_t)d * LL + c * 4);
    }
    #pragma unroll
    for (int p = 0; p < 8; p++) {
        int idx = p * 256 + t;
        int d = idx >> 5, c = idx & 31;
        *(float4*)&Ks[d][c * 4] = *(const float4*)(kb + (size_t)d * LL + c * 4);
    }
    __syncthreads();

    ull acc[4][4] = {};   // [i][0..1]: cols tm*4+{01,23}; [i][2..3]: cols 64+tm*4+{01,23}

    #pragma unroll 8
    for (int d = 0; d < 64; d++) {
        float4 a4 = *(float4*)&Qs[d][tr * 4];
        ulonglong2 b0 = *(ulonglong2*)&Ks[d][tm * 4];
        ulonglong2 b1 = *(ulonglong2*)&Ks[d][64 + tm * 4];
        ull ad0 = pk2(a4.x, a4.x);
        ull ad1 = pk2(a4.y, a4.y);
        ull ad2 = pk2(a4.z, a4.z);
        ull ad3 = pk2(a4.w, a4.w);
        ffma2(acc[0][0], ad0, b0.x); ffma2(acc[0][1], ad0, b0.y);
        ffma2(acc[0][2], ad0, b1.x); ffma2(acc[0][3], ad0, b1.y);
        ffma2(acc[1][0], ad1, b0.x); ffma2(acc[1][1], ad1, b0.y);
        ffma2(acc[1][2], ad1, b1.x); ffma2(acc[1][3], ad1, b1.y);
        ffma2(acc[2][0], ad2, b0.x); ffma2(acc[2][1], ad2, b0.y);
        ffma2(acc[2][2], ad2, b1.x); ffma2(acc[2][3], ad2, b1.y);
        ffma2(acc[3][0], ad3, b0.x); ffma2(acc[3][1], ad3, b0.y);
        ffma2(acc[3][2], ad3, b1.x); ffma2(acc[3][3], ad3, b1.y);
    }

    float s = 0.f, s2 = 0.f;
    float* simb = g_sim + (size_t)bh * LL * LL + (size_t)l0 * LL + m0;
    #pragma unroll
    for (int i = 0; i < 4; i++) {
        float2 v0 = upk(acc[i][0]), v1 = upk(acc[i][1]);
        float2 v2 = upk(acc[i][2]), v3 = upk(acc[i][3]);
        float4 w0; w0.x = v0.x; w0.y = v0.y; w0.z = v1.x; w0.w = v1.y;
        float4 w1; w1.x = v2.x; w1.y = v2.y; w1.z = v3.x; w1.w = v3.y;
        size_t ro = (size_t)(tr * 4 + i) * LL;
        *(float4*)(simb + ro + tm * 4) = w0;
        *(float4*)(simb + ro + 64 + tm * 4) = w1;
        s += ((w0.x + w0.y) + (w0.z + w0.w)) + ((w1.x + w1.y) + (w1.z + w1.w));
        s2 = fmaf(w0.x, w0.x, s2); s2 = fmaf(w0.y, w0.y, s2);
        s2 = fmaf(w0.z, w0.z, s2); s2 = fmaf(w0.w, w0.w, s2);
        s2 = fmaf(w1.x, w1.x, s2); s2 = fmaf(w1.y, w1.y, s2);
        s2 = fmaf(w1.z, w1.z, s2); s2 = fmaf(w1.w, w1.w, s2);
    }

    #pragma unroll
    for (int o = 16; o > 0; o >>= 1) {
        s  += __shfl_down_sync(0xffffffffu, s,  o);
        s2 += __shfl_down_sync(0xffffffffu, s2, o);
    }
    __shared__ float ws[8], wq[8];
    if ((t & 31) == 0) { ws[t >> 5] = s; wq[t >> 5] = s2; }
    __syncthreads();
    if (t == 0) {
        float ts = 0.f, tq = 0.f;
        #pragma unroll
        for (int w = 0; w < 8; w++) { ts += ws[w]; tq += wq[w]; }
        int bid = bh * 512 + blockIdx.y * 16 + blockIdx.x;
        g_p1s[bid] = ts;
        g_p1q[bid] = tq;
    }
}

// ---------------- K1b: per-batch rstd of sim (deterministic) ----------------
__global__ void __launch_bounds__(256) k1_stats() {
    const int n = blockIdx.x;
    const int t = threadIdx.x;
    const int base = n * 4096;   // 8 heads * 512 blocks
    float s = 0.f, q = 0.f;
    for (int i = t; i < 4096; i += 256) { s += g_p1s[base + i]; q += g_p1q[base + i]; }
    #pragma unroll
    for (int o = 16; o > 0; o >>= 1) {
        s += __shfl_down_sync(0xffffffffu, s, o);
        q += __shfl_down_sync(0xffffffffu, q, o);
    }
    __shared__ float ws[8], wq[8];
    if ((t & 31) == 0) { ws[t >> 5] = s; wq[t >> 5] = q; }
    __syncthreads();
    if (t == 0) {
        float ts = 0.f, tq = 0.f;
        #pragma unroll
        for (int w = 0; w < 8; w++) { ts += ws[w]; tq += wq[w]; }
        const float inv_cnt = 1.0f / 33554432.0f;   // H*L*L
        float mean = ts * inv_cnt;
        float var  = tq * inv_cnt - mean * mean;
        g_escale[n] = rsqrtf(var + 1e-5f) * 1.4426950408889634f;
    }
}

// ---------------- K3: rv[c,l] = softmax_m(rstd*sim[l,m]) @ V[c,m], + LN2 partials ----------------
__global__ void __launch_bounds__(256) k3_attnv(const float* __restrict__ V,
                                                float* __restrict__ out) {
    __shared__ __align__(16) float Ps[64][68];
    __shared__ __align__(16) float Vs[64][68];
    __shared__ float rs[64];
    const int bh = blockIdx.y;
    const int l0 = blockIdx.x * 64;
    const float csf = g_escale[bh >> 3];
    const float* simb = g_sim + (size_t)bh * LL * LL + (size_t)l0 * LL;
    const float* vb   = V + (size_t)bh * CC * LL;
    const int t  = threadIdx.x;
    const int tm = t & 15;
    const int tr = t >> 4;

    const ull cs2    = pk2(csf, csf);
    const ull MAGIC  = pk2(12582912.0f, 12582912.0f);
    const ull NMAGIC = pk2(-12582912.0f, -12582912.0f);
    const ull NEG1   = pk2(-1.0f, -1.0f);
    const ull C5     = pk2(1.3333558146428443e-3f, 1.3333558146428443e-3f);
    const ull C4     = pk2(9.6181291076284770e-3f, 9.6181291076284770e-3f);
    const ull C3     = pk2(5.5504108664821580e-2f, 5.5504108664821580e-2f);
    const ull C2     = pk2(2.4022650695910071e-1f, 2.4022650695910071e-1f);
    const ull C1     = pk2(6.9314718055994531e-1f, 6.9314718055994531e-1f);
    const ull ONE2   = pk2(1.0f, 1.0f);

    ull acc[4][4] = {};        // packed over m-parity; [i=c][j=l]
    ull rsum2[4] = {};

    for (int mc = 0; mc < 32; mc++) {
        const int m0 = mc * 64;
        __syncthreads();
        #pragma unroll
        for (int p = 0; p < 4; p++) {
            int row = p * 16 + tr;
            ulonglong2 sv = *(const ulonglong2*)(simb + (size_t)row * LL + m0 + tm * 4);
            ull p0 = pexp2(sv.x, cs2, MAGIC, NMAGIC, NEG1, C5, C4, C3, C2, C1, ONE2);
            ull p1 = pexp2(sv.y, cs2, MAGIC, NMAGIC, NEG1, C5, C4, C3, C2, C1, ONE2);
            rsum2[p] = fadd2(rsum2[p], fadd2(p0, p1));
            ulonglong2 pv; pv.x = p0; pv.y = p1;
            *(ulonglong2*)&Ps[row][tm * 4] = pv;
            *(ulonglong2*)&Vs[row][tm * 4] = *(const ulonglong2*)(vb + (size_t)row * LL + m0 + tm * 4);
        }
        __syncthreads();
        #pragma unroll 2
        for (int m4 = 0; m4 < 64; m4 += 4) {
            ulonglong2 pj[4], vi[4];
            #pragma unroll
            for (int j = 0; j < 4; j++) pj[j] = *(ulonglong2*)&Ps[tm + 16 * j][m4];
            #pragma unroll
            for (int i = 0; i < 4; i++) vi[i] = *(ulonglong2*)&Vs[tr + 16 * i][m4];
            #pragma unroll
            for (int i = 0; i < 4; i++)
                #pragma unroll
                for (int j = 0; j < 4; j++) {
                    ffma2(acc[i][j], vi[i].x, pj[j].x);
                    ffma2(acc[i][j], vi[i].y, pj[j].y);
                }
        }
    }

    // rowsum: fold packed halves, then reduce across the 16 lanes sharing each row
    float rsum[4];
    #pragma unroll
    for (int p = 0; p < 4; p++) { float2 r = upk(rsum2[p]); rsum[p] = r.x + r.y; }
    #pragma unroll
    for (int o = 8; o > 0; o >>= 1)
        #pragma unroll
        for (int p = 0; p < 4; p++)
            rsum[p] += __shfl_xor_sync(0xffffffffu, rsum[p], o);
    if (tm == 0)
        #pragma unroll
        for (int p = 0; p < 4; p++) rs[p * 16 + tr] = rsum[p];
    __syncthreads();

    float inv[4];
    #pragma unroll
    for (int j = 0; j < 4; j++) inv[j] = 1.0f / rs[tm + 16 * j];

    float s = 0.f, s2 = 0.f;
    float* ob = out + (size_t)bh * CC * LL + l0;
    #pragma unroll
    for (int i = 0; i < 4; i++) {
        int c = tr + 16 * i;
        #pragma unroll
        for (int j = 0; j < 4; j++) {
            float2 a = upk(acc[i][j]);
            float val = (a.x + a.y) * inv[j];
            ob[(size_t)c * LL + tm + 16 * j] = val;
            s += val;
            s2 = fmaf(val, val, s2);
        }
    }

    #pragma unroll
    for (int o = 16; o > 0; o >>= 1) {
        s  += __shfl_down_sync(0xffffffffu, s,  o);
        s2 += __shfl_down_sync(0xffffffffu, s2, o);
    }
    __shared__ float ws[8], wq[8];
    if ((t & 31) == 0) { ws[t >> 5] = s; wq[t >> 5] = s2; }
    __syncthreads();
    if (t == 0) {
        float ts = 0.f, tq = 0.f;
        #pragma unroll
        for (int w = 0; w < 8; w++) { ts += ws[w]; tq += wq[w]; }
        int bid = bh * 32 + blockIdx.x;
        g_p2s[bid] = ts;
        g_p2q[bid] = tq;
    }
}

// ---------------- K3b: per-batch mean/rstd of rv ----------------
__global__ void __launch_bounds__(256) k3_stats() {
    const int n = blockIdx.x;
    const int t = threadIdx.x;
    float s = g_p2s[n * 256 + t];
    float q = g_p2q[n * 256 + t];
    #pragma unroll
    for (int o = 16; o > 0; o >>= 1) {
        s += __shfl_down_sync(0xffffffffu, s, o);
        q += __shfl_down_sync(0xffffffffu, q, o);
    }
    __shared__ float ws[8], wq[8];
    if ((t & 31) == 0) { ws[t >> 5] = s; wq[t >> 5] = q; }
    __syncthreads();
    if (t == 0) {
        float ts = 0.f, tq = 0.f;
        #pragma unroll
        for (int w = 0; w < 8; w++) { ts += ws[w]; tq += wq[w]; }
        const float inv_cnt = 1.0f / 1048576.0f;   // H*C*L
        float mean = ts * inv_cnt;
        float var  = tq * inv_cnt - mean * mean;
        g_mean2[n] = mean;
        g_rstd2[n] = rsqrtf(var + 1e-5f);
    }
}

// ---------------- K4: in-place LayerNorm + exact GELU ----------------
__global__ void __launch_bounds__(256) k4_lngelu(float* __restrict__ out) {
    int idx = blockIdx.x * 256 + threadIdx.x;
    int n = idx >> 20;                 // H*C*L = 2^20 per batch
    float x = (out[idx] - g_mean2[n]) * g_rstd2[n];
    out[idx] = 0.5f * x * (1.0f + erff(x * 0.70710678118654752f));
}

// ---------------- launch ----------------
extern "C" void kernel_launch(void* const* d_in, const int* in_sizes, int n_in,
                              void* d_out, int out_size) {
    (void)in_sizes; (void)n_in; (void)out_size;
    const float* Q = (const float*)d_in[0];
    const float* K = (const float*)d_in[1];
    const float* V = (const float*)d_in[2];
    float* out = (float*)d_out;

    k1_sim  <<<dim3(16, 32, 32), 256>>>(Q, K);
    k1_stats<<<4, 256>>>();
    k3_attnv<<<dim3(32, 32), 256>>>(V, out);
    k3_stats<<<4, 256>>>();
    k4_lngelu<<<16384, 256>>>(out);
}

// round 5
// speedup vs baseline: 1.0051x; 1.0051x over previous
#include <cuda_runtime.h>
#include <math.h>

#define NB 4
#define HH 8
#define DD 64
#define LL 2048
#define CC 64
#define BH (NB * HH)   // 32

typedef unsigned long long ull;

// ---------------- device scratch (no allocations allowed) ----------------
__device__ float g_sim[(size_t)BH * LL * LL];   // 512 MB sim scratch
__device__ float g_p1s[BH * 512];
__device__ float g_p1q[BH * 512];
__device__ float g_p2s[BH * 32];
__device__ float g_p2q[BH * 32];
__device__ float g_escale[NB];                  // rstd1 * log2(e)
__device__ float g_mean2[NB];
__device__ float g_rstd2[NB];

// ---------------- packed f32x2 helpers (Blackwell FFMA2 path) ----------------
__device__ __forceinline__ ull pk2(float a, float b) {
    ull r; asm("mov.b64 %0,{%1,%2};" : "=l"(r) : "f"(a), "f"(b)); return r;
}
__device__ __forceinline__ float2 upk(ull p) {
    float2 r; asm("mov.b64 {%0,%1},%2;" : "=f"(r.x), "=f"(r.y) : "l"(p)); return r;
}
__device__ __forceinline__ void ffma2(ull& d, ull a, ull b) {
    asm("fma.rn.f32x2 %0,%1,%2,%0;" : "+l"(d) : "l"(a), "l"(b));
}
__device__ __forceinline__ ull ffma2r(ull a, ull b, ull c) {
    ull d; asm("fma.rn.f32x2 %0,%1,%2,%3;" : "=l"(d) : "l"(a), "l"(b), "l"(c)); return d;
}
__device__ __forceinline__ ull fmul2(ull a, ull b) {
    ull d; asm("mul.rn.f32x2 %0,%1,%2;" : "=l"(d) : "l"(a), "l"(b)); return d;
}
__device__ __forceinline__ ull fadd2(ull a, ull b) {
    ull d; asm("add.rn.f32x2 %0,%1,%2;" : "=l"(d) : "l"(a), "l"(b)); return d;
}

// packed exp(s * rstd) via exp2 polynomial, 2 elements at a time on the fma pipe
__device__ __forceinline__ ull pexp2(ull s2, ull cs2, ull MAGIC, ull NMAGIC, ull NEG1,
                                     ull C5, ull C4, ull C3, ull C2, ull C1, ull ONE2) {
    ull y = fmul2(s2, cs2);
    ull t = fadd2(y, MAGIC);           // round-to-nearest int in low mantissa
    ull u = fadd2(t, NMAGIC);          // t - magic (= round(y))
    ull f = ffma2r(u, NEG1, y);        // f = y - round(y), in [-0.5, 0.5]
    ull p = ffma2r(C5, f, C4);
    p = ffma2r(p, f, C3);
    p = ffma2r(p, f, C2);
    p = ffma2r(p, f, C1);
    p = ffma2r(p, f, ONE2);            // 2^f
    float2 tf = upk(t);
    int k0 = (__float_as_int(tf.x) << 23) + 0x3f800000;
    int k1 = (__float_as_int(tf.y) << 23) + 0x3f800000;
    ull sc = pk2(__int_as_float(k0), __int_as_float(k1));
    return fmul2(p, sc);               // 2^f * 2^k
}

// ---------------- K1: sim = Q^T K per (b,h), + per-block sum/sumsq ----------------
// block tile 64(l) x 128(m), per-thread 4x8 via packed FFMA2
__global__ void __launch_bounds__(256) k1_sim(const float* __restrict__ Q,
                                              const float* __restrict__ K) {
    __shared__ __align__(16) float Qs[64][64];
    __shared__ __align__(16) float Ks[64][128];
    const int bh = blockIdx.z;
    const int l0 = blockIdx.y * 64;
    const int m0 = blockIdx.x * 128;
    const int t  = threadIdx.x;
    const int tm = t & 15;     // 0..15 (cols tm*4 and 64+tm*4)
    const int tr = t >> 4;     // 0..15 (rows tr*4..tr*4+3)

    const float* qb = Q + (size_t)bh * DD * LL + l0;
    const float* kb = K + (size_t)bh * DD * LL + m0;

    #pragma unroll
    for (int p = 0; p < 4; p++) {
        int idx = p * 256 + t;
        int d = idx >> 4, c = idx & 15;
        *(float4*)&Qs[d][c * 4] = *(const float4*)(qb + (size_t)d * LL + c * 4);
    }
    #pragma unroll
    for (int p = 0; p < 8; p++) {
        int idx = p * 256 + t;
        int d = idx >> 5, c = idx & 31;
        *(float4*)&Ks[d][c * 4] = *(const float4*)(kb + (size_t)d * LL + c * 4);
    }
    __syncthreads();

    ull acc[4][4] = {};   // [i][0..1]: cols tm*4+{01,23}; [i][2..3]: cols 64+tm*4+{01,23}

    #pragma unroll 8
    for (int d = 0; d < 64; d++) {
        float4 a4 = *(float4*)&Qs[d][tr * 4];
        ulonglong2 b0 = *(ulonglong2*)&Ks[d][tm * 4];
        ulonglong2 b1 = *(ulonglong2*)&Ks[d][64 + tm * 4];
        ull ad0 = pk2(a4.x, a4.x);
        ull ad1 = pk2(a4.y, a4.y);
        ull ad2 = pk2(a4.z, a4.z);
        ull ad3 = pk2(a4.w, a4.w);
        ffma2(acc[0][0], ad0, b0.x); ffma2(acc[0][1], ad0, b0.y);
        ffma2(acc[0][2], ad0, b1.x); ffma2(acc[0][3], ad0, b1.y);
        ffma2(acc[1][0], ad1, b0.x); ffma2(acc[1][1], ad1, b0.y);
        ffma2(acc[1][2], ad1, b1.x); ffma2(acc[1][3], ad1, b1.y);
        ffma2(acc[2][0], ad2, b0.x); ffma2(acc[2][1], ad2, b0.y);
        ffma2(acc[2][2], ad2, b1.x); ffma2(acc[2][3], ad2, b1.y);
        ffma2(acc[3][0], ad3, b0.x); ffma2(acc[3][1], ad3, b0.y);
        ffma2(acc[3][2], ad3, b1.x); ffma2(acc[3][3], ad3, b1.y);
    }

    float s = 0.f, s2 = 0.f;
    float* simb = g_sim + (size_t)bh * LL * LL + (size_t)l0 * LL + m0;
    #pragma unroll
    for (int i = 0; i < 4; i++) {
        float2 v0 = upk(acc[i][0]), v1 = upk(acc[i][1]);
        float2 v2 = upk(acc[i][2]), v3 = upk(acc[i][3]);
        float4 w0; w0.x = v0.x; w0.y = v0.y; w0.z = v1.x; w0.w = v1.y;
        float4 w1; w1.x = v2.x; w1.y = v2.y; w1.z = v3.x; w1.w = v3.y;
        size_t ro = (size_t)(tr * 4 + i) * LL;
        *(float4*)(simb + ro + tm * 4) = w0;
        *(float4*)(simb + ro + 64 + tm * 4) = w1;
        s += ((w0.x + w0.y) + (w0.z + w0.w)) + ((w1.x + w1.y) + (w1.z + w1.w));
        s2 = fmaf(w0.x, w0.x, s2); s2 = fmaf(w0.y, w0.y, s2);
        s2 = fmaf(w0.z, w0.z, s2); s2 = fmaf(w0.w, w0.w, s2);
        s2 = fmaf(w1.x, w1.x, s2); s2 = fmaf(w1.y, w1.y, s2);
        s2 = fmaf(w1.z, w1.z, s2); s2 = fmaf(w1.w, w1.w, s2);
    }

    #pragma unroll
    for (int o = 16; o > 0; o >>= 1) {
        s  += __shfl_down_sync(0xffffffffu, s,  o);
        s2 += __shfl_down_sync(0xffffffffu, s2, o);
    }
    __shared__ float ws[8], wq[8];
    if ((t & 31) == 0) { ws[t >> 5] = s; wq[t >> 5] = s2; }
    __syncthreads();
    if (t == 0) {
        float ts = 0.f, tq = 0.f;
        #pragma unroll
        for (int w = 0; w < 8; w++) { ts += ws[w]; tq += wq[w]; }
        int bid = bh * 512 + blockIdx.y * 16 + blockIdx.x;
        g_p1s[bid] = ts;
        g_p1q[bid] = tq;
    }
}

// ---------------- K1b: per-batch rstd of sim (deterministic) ----------------
__global__ void __launch_bounds__(256) k1_stats() {
    const int n = blockIdx.x;
    const int t = threadIdx.x;
    const int base = n * 4096;   // 8 heads * 512 blocks
    float s = 0.f, q = 0.f;
    for (int i = t; i < 4096; i += 256) { s += g_p1s[base + i]; q += g_p1q[base + i]; }
    #pragma unroll
    for (int o = 16; o > 0; o >>= 1) {
        s += __shfl_down_sync(0xffffffffu, s, o);
        q += __shfl_down_sync(0xffffffffu, q, o);
    }
    __shared__ float ws[8], wq[8];
    if ((t & 31) == 0) { ws[t >> 5] = s; wq[t >> 5] = q; }
    __syncthreads();
    if (t == 0) {
        float ts = 0.f, tq = 0.f;
        #pragma unroll
        for (int w = 0; w < 8; w++) { ts += ws[w]; tq += wq[w]; }
        const float inv_cnt = 1.0f / 33554432.0f;   // H*L*L
        float mean = ts * inv_cnt;
        float var  = tq * inv_cnt - mean * mean;
        g_escale[n] = rsqrtf(var + 1e-5f) * 1.4426950408889634f;
    }
}

// ---------------- K3: rv[c,l] = softmax_m(rstd*sim[l,m]) @ V[c,m], + LN2 partials ----------------
__global__ void __launch_bounds__(256) k3_attnv(const float* __restrict__ V,
                                                float* __restrict__ out) {
    __shared__ __align__(16) float Ps[64][68];
    __shared__ __align__(16) float Vs[64][68];
    __shared__ float rs[64];
    const int bh = blockIdx.y;
    const int l0 = blockIdx.x * 64;
    const float csf = g_escale[bh >> 3];
    const float* simb = g_sim + (size_t)bh * LL * LL + (size_t)l0 * LL;
    const float* vb   = V + (size_t)bh * CC * LL;
    const int t  = threadIdx.x;
    const int tm = t & 15;
    const int tr = t >> 4;

    const ull cs2    = pk2(csf, csf);
    const ull MAGIC  = pk2(12582912.0f, 12582912.0f);
    const ull NMAGIC = pk2(-12582912.0f, -12582912.0f);
    const ull NEG1   = pk2(-1.0f, -1.0f);
    const ull C5     = pk2(1.3333558146428443e-3f, 1.3333558146428443e-3f);
    const ull C4     = pk2(9.6181291076284770e-3f, 9.6181291076284770e-3f);
    const ull C3     = pk2(5.5504108664821580e-2f, 5.5504108664821580e-2f);
    const ull C2     = pk2(2.4022650695910071e-1f, 2.4022650695910071e-1f);
    const ull C1     = pk2(6.9314718055994531e-1f, 6.9314718055994531e-1f);
    const ull ONE2   = pk2(1.0f, 1.0f);

    ull acc[4][4] = {};        // packed over m-parity; [i=c][j=l]
    ull rsum2[4] = {};

    for (int mc = 0; mc < 32; mc++) {
        const int m0 = mc * 64;
        __syncthreads();
        #pragma unroll
        for (int p = 0; p < 4; p++) {
            int row = p * 16 + tr;
            ulonglong2 sv = *(const ulonglong2*)(simb + (size_t)row * LL + m0 + tm * 4);
            ull p0 = pexp2(sv.x, cs2, MAGIC, NMAGIC, NEG1, C5, C4, C3, C2, C1, ONE2);
            ull p1 = pexp2(sv.y, cs2, MAGIC, NMAGIC, NEG1, C5, C4, C3, C2, C1, ONE2);
            rsum2[p] = fadd2(rsum2[p], fadd2(p0, p1));
            ulonglong2 pv; pv.x = p0; pv.y = p1;
            *(ulonglong2*)&Ps[row][tm * 4] = pv;
            *(ulonglong2*)&Vs[row][tm * 4] = *(const ulonglong2*)(vb + (size_t)row * LL + m0 + tm * 4);
        }
        __syncthreads();
        #pragma unroll 2
        for (int m4 = 0; m4 < 64; m4 += 4) {
            ulonglong2 pj[4], vi[4];
            #pragma unroll
            for (int j = 0; j < 4; j++) pj[j] = *(ulonglong2*)&Ps[tm + 16 * j][m4];
            #pragma unroll
            for (int i = 0; i < 4; i++) vi[i] = *(ulonglong2*)&Vs[tr + 16 * i][m4];
            #pragma unroll
            for (int i = 0; i < 4; i++)
                #pragma unroll
                for (int j = 0; j < 4; j++) {
                    ffma2(acc[i][j], vi[i].x, pj[j].x);
                    ffma2(acc[i][j], vi[i].y, pj[j].y);
                }
        }
    }

    // rowsum: fold packed halves, then reduce across the 16 lanes sharing each row
    float rsum[4];
    #pragma unroll
    for (int p = 0; p < 4; p++) { float2 r = upk(rsum2[p]); rsum[p] = r.x + r.y; }
    #pragma unroll
    for (int o = 8; o > 0; o >>= 1)
        #pragma unroll
        for (int p = 0; p < 4; p++)
            rsum[p] += __shfl_xor_sync(0xffffffffu, rsum[p], o);
    if (tm == 0)
        #pragma unroll
        for (int p = 0; p < 4; p++) rs[p * 16 + tr] = rsum[p];
    __syncthreads();

    float inv[4];
    #pragma unroll
    for (int j = 0; j < 4; j++) inv[j] = 1.0f / rs[tm + 16 * j];

    float s = 0.f, s2 = 0.f;
    float* ob = out + (size_t)bh * CC * LL + l0;
    #pragma unroll
    for (int i = 0; i < 4; i++) {
        int c = tr + 16 * i;
        #pragma unroll
        for (int j = 0; j < 4; j++) {
            float2 a = upk(acc[i][j]);
            float val = (a.x + a.y) * inv[j];
            ob[(size_t)c * LL + tm + 16 * j] = val;
            s += val;
            s2 = fmaf(val, val, s2);
        }
    }

    #pragma unroll
    for (int o = 16; o > 0; o >>= 1) {
        s  += __shfl_down_sync(0xffffffffu, s,  o);
        s2 += __shfl_down_sync(0xffffffffu, s2, o);
    }
    __shared__ float ws[8], wq[8];
    if ((t & 31) == 0) { ws[t >> 5] = s; wq[t >> 5] = s2; }
    __syncthreads();
    if (t == 0) {
        float ts = 0.f, tq = 0.f;
        #pragma unroll
        for (int w = 0; w < 8; w++) { ts += ws[w]; tq += wq[w]; }
        int bid = bh * 32 + blockIdx.x;
        g_p2s[bid] = ts;
        g_p2q[bid] = tq;
    }
}

// ---------------- K3b: per-batch mean/rstd of rv ----------------
__global__ void __launch_bounds__(256) k3_stats() {
    const int n = blockIdx.x;
    const int t = threadIdx.x;
    float s = g_p2s[n * 256 + t];
    float q = g_p2q[n * 256 + t];
    #pragma unroll
    for (int o = 16; o > 0; o >>= 1) {
        s += __shfl_down_sync(0xffffffffu, s, o);
        q += __shfl_down_sync(0xffffffffu, q, o);
    }
    __shared__ float ws[8], wq[8];
    if ((t & 31) == 0) { ws[t >> 5] = s; wq[t >> 5] = q; }
    __syncthreads();
    if (t == 0) {
        float ts = 0.f, tq = 0.f;
        #pragma unroll
        for (int w = 0; w < 8; w++) { ts += ws[w]; tq += wq[w]; }
        const float inv_cnt = 1.0f / 1048576.0f;   // H*C*L
        float mean = ts * inv_cnt;
        float var  = tq * inv_cnt - mean * mean;
        g_mean2[n] = mean;
        g_rstd2[n] = rsqrtf(var + 1e-5f);
    }
}

// ---------------- K4: in-place LayerNorm + exact GELU ----------------
__global__ void __launch_bounds__(256) k4_lngelu(float* __restrict__ out) {
    int idx = blockIdx.x * 256 + threadIdx.x;
    int n = idx >> 20;                 // H*C*L = 2^20 per batch
    float x = (out[idx] - g_mean2[n]) * g_rstd2[n];
    out[idx] = 0.5f * x * (1.0f + erff(x * 0.70710678118654752f));
}

// ---------------- launch ----------------
extern "C" void kernel_launch(void* const* d_in, const int* in_sizes, int n_in,
                              void* d_out, int out_size) {
    (void)in_sizes; (void)n_in; (void)out_size;
    const float* Q = (const float*)d_in[0];
    const float* K = (const float*)d_in[1];
    const float* V = (const float*)d_in[2];
    float* out = (float*)d_out;

    k1_sim  <<<dim3(16, 32, 32), 256>>>(Q, K);
    k1_stats<<<4, 256>>>();
    k3_attnv<<<dim3(32, 32), 256>>>(V, out);
    k3_stats<<<4, 256>>>();
    k4_lngelu<<<16384, 256>>>(out);
}